// round 1
// baseline (speedup 1.0000x reference)
#include <cuda_runtime.h>

// ---------------------------------------------------------------------------
// Inverse DTCWT, 2 levels. Shapes (fixed):
//   low   : (8, 256, 256, 3)
//   high0 : (8, 256, 256, 36)
//   high1 : (8, 128, 128, 36)
//   out   : (8, 512, 512, 3)
// ---------------------------------------------------------------------------

#define SCQ 0.70710678118654752f

// qshift phase-filter tables (derived from 14-tap G0A/G0B/G1A/G1B, split into
// even/odd polyphase per output phase s = n & 3).
// g0 pair (ha=G0B, hb=G0A): source base = 2k + 6 + (s&1)
// g1 pair (ha=G1B, hb=G1A): source base = 2k + 7 - (s&1)
__device__ const float F0[4][7] = {
  { 0.00325314f,  0.03466035f, -0.11720389f,  0.75614564f,  0.01186609f,  0.02382538f, -0.00543948f},
  {-0.00455690f,  0.01702522f, -0.10671180f,  0.56881042f,  0.27529538f, -0.03887280f, -0.00388321f},
  {-0.00388321f, -0.03887280f,  0.27529538f,  0.56881042f, -0.10671180f,  0.01702522f, -0.00455690f},
  {-0.00543948f,  0.02382538f,  0.01186609f,  0.75614564f, -0.11720389f,  0.03466035f,  0.00325314f}
};
__device__ const float F1[4][7] = {
  {-0.00455690f,  0.01702522f, -0.10671180f,  0.56881042f,  0.27529538f, -0.03887280f, -0.00388321f},
  {-0.00325314f, -0.03466035f,  0.11720389f, -0.75614564f, -0.01186609f, -0.02382538f,  0.00543948f},
  { 0.00543948f, -0.02382538f, -0.01186609f, -0.75614564f,  0.11720389f, -0.03466035f, -0.00325314f},
  {-0.00388321f, -0.03887280f,  0.27529538f,  0.56881042f, -0.10671180f,  0.01702522f, -0.00455690f}
};

// biort synthesis filters (odd length, size-preserving)
__device__ const float G0O[7] = {-0.0107142857142857f, -0.0535714285714286f, 0.2607142857142857f,
                                  0.6071428571428571f,  0.2607142857142857f, -0.0535714285714286f,
                                 -0.0107142857142857f};
__device__ const float G1O[5] = {-0.05f, -0.25f, 0.6f, -0.25f, -0.05f};

// scratch (device globals; no allocations allowed)
__device__ float g_Y1 [8 * 512 * 256 * 3];
__device__ float g_Y2 [8 * 512 * 256 * 3];
__device__ float g_Z  [8 * 512 * 512 * 3];
__device__ float g_Y1b[8 * 512 * 512 * 3];
__device__ float g_Y2b[8 * 512 * 512 * 3];

__device__ __forceinline__ int refl(int p, int L) {
  // half-sample symmetric reflection (single bounce is sufficient here)
  return p < 0 ? (-1 - p) : (p >= L ? (2 * L - 1 - p) : p);
}

// c2q on the fly from a 36-channel "high" tensor.
// p: row index in the 2x-expanded c2q image; w: col index in expanded image.
__device__ __forceinline__ float c2q(const float* __restrict__ hi, int b, int H, int W,
                                     int p, int w, int c, int sa, int sb) {
  int i = p >> 1, j = w >> 1, rp = p & 1, wp = w & 1;
  const float* base = hi + ((((b * H) + i) * W + j) * 36);
  int im = (rp ^ wp) ? 18 : 0;
  float x = base[im + 3 * sa + c];
  float y = base[im + 3 * sb + c];
  float v = (rp == 0) ? (x + y) : ((wp == 0) ? (x - y) : (y - x));
  return v * SCQ;
}

// ---------------- Kernel 1: level-1 vertical (colifilt over H) --------------
// Y1 = colifilt(low, g0) + colifilt(lh1, g1) ;  Y2 = colifilt(hl1, g0) + colifilt(hh1, g1)
// out rows: 512, cols: 256, C=3
__global__ void k1_lvl1_vert(const float* __restrict__ low, const float* __restrict__ high1) {
  int idx = blockIdx.x * blockDim.x + threadIdx.x;
  const int TOT = 8 * 512 * 256 * 3;
  if (idx >= TOT) return;
  int c = idx % 3;
  int t = idx / 3;
  int w = t % 256; t /= 256;
  int n = t % 512;
  int b = t / 512;
  int k = n >> 2, s = n & 3;
  int off0 = 2 * k + 6 + (s & 1);
  int off1 = 2 * k + 7 - (s & 1);
  float a1 = 0.f, a2 = 0.f;
#pragma unroll
  for (int j = 0; j < 7; j++) {
    int p = refl(off0 - 2 * j, 256);
    float f = F0[s][j];
    a1 += f * low[(((b * 256) + p) * 256 + w) * 3 + c];
    a2 += f * c2q(high1, b, 128, 128, p, w, c, 2, 3);   // hl
  }
#pragma unroll
  for (int j = 0; j < 7; j++) {
    int p = refl(off1 - 2 * j, 256);
    float f = F1[s][j];
    a1 += f * c2q(high1, b, 128, 128, p, w, c, 0, 5);   // lh
    a2 += f * c2q(high1, b, 128, 128, p, w, c, 1, 4);   // hh
  }
  g_Y1[idx] = a1;
  g_Y2[idx] = a2;
}

// ---------------- Kernel 2: level-1 horizontal (colifilt over W) ------------
// Z[b,h,wn,c] = colifilt_w(Y1, g0) + colifilt_w(Y2, g1)
__global__ void k2_lvl1_horz() {
  int idx = blockIdx.x * blockDim.x + threadIdx.x;
  const int TOT = 8 * 512 * 512 * 3;
  if (idx >= TOT) return;
  int c = idx % 3;
  int t = idx / 3;
  int wn = t % 512; t /= 512;
  int h  = t % 512;
  int b  = t / 512;
  int k = wn >> 2, s = wn & 3;
  int off0 = 2 * k + 6 + (s & 1);
  int off1 = 2 * k + 7 - (s & 1);
  int rowbase = ((b * 512 + h) * 256) * 3 + c;
  float acc = 0.f;
#pragma unroll
  for (int j = 0; j < 7; j++) {
    int p = refl(off0 - 2 * j, 256);
    acc += F0[s][j] * g_Y1[rowbase + p * 3];
  }
#pragma unroll
  for (int j = 0; j < 7; j++) {
    int p = refl(off1 - 2 * j, 256);
    acc += F1[s][j] * g_Y2[rowbase + p * 3];
  }
  g_Z[idx] = acc;
}

// ---------------- Kernel 3: level-0 vertical (colfilter over H) -------------
// Y1b = colfilter(Z, G0O) + colfilter(lh0, G1O)
// Y2b = colfilter(hl0, G0O) + colfilter(hh0, G1O)
__global__ void k3_lvl0_vert(const float* __restrict__ high0) {
  int idx = blockIdx.x * blockDim.x + threadIdx.x;
  const int TOT = 8 * 512 * 512 * 3;
  if (idx >= TOT) return;
  int c = idx % 3;
  int t = idx / 3;
  int w = t % 512; t /= 512;
  int h = t % 512;
  int b = t / 512;
  float a1 = 0.f, a2 = 0.f;
#pragma unroll
  for (int j = 0; j < 7; j++) {
    int p = refl(h + 3 - j, 512);
    float f = G0O[j];
    a1 += f * g_Z[((b * 512 + p) * 512 + w) * 3 + c];
    a2 += f * c2q(high0, b, 256, 256, p, w, c, 2, 3);   // hl
  }
#pragma unroll
  for (int j = 0; j < 5; j++) {
    int p = refl(h + 2 - j, 512);
    float f = G1O[j];
    a1 += f * c2q(high0, b, 256, 256, p, w, c, 0, 5);   // lh
    a2 += f * c2q(high0, b, 256, 256, p, w, c, 1, 4);   // hh
  }
  g_Y1b[idx] = a1;
  g_Y2b[idx] = a2;
}

// ---------------- Kernel 4: level-0 horizontal (colfilter over W) -----------
__global__ void k4_lvl0_horz(float* __restrict__ out) {
  int idx = blockIdx.x * blockDim.x + threadIdx.x;
  const int TOT = 8 * 512 * 512 * 3;
  if (idx >= TOT) return;
  int c = idx % 3;
  int t = idx / 3;
  int w = t % 512; t /= 512;
  int h = t % 512;
  int b = t / 512;
  int rowbase = ((b * 512 + h) * 512) * 3 + c;
  float acc = 0.f;
#pragma unroll
  for (int j = 0; j < 7; j++) {
    int p = refl(w + 3 - j, 512);
    acc += G0O[j] * g_Y1b[rowbase + p * 3];
  }
#pragma unroll
  for (int j = 0; j < 5; j++) {
    int p = refl(w + 2 - j, 512);
    acc += G1O[j] * g_Y2b[rowbase + p * 3];
  }
  out[idx] = acc;
}

extern "C" void kernel_launch(void* const* d_in, const int* in_sizes, int n_in,
                              void* d_out, int out_size) {
  // identify inputs by element count (robust to ordering)
  const float *low = nullptr, *high0 = nullptr, *high1 = nullptr;
  for (int i = 0; i < n_in; i++) {
    if (in_sizes[i] == 8 * 256 * 256 * 3)       low   = (const float*)d_in[i];
    else if (in_sizes[i] == 8 * 256 * 256 * 36) high0 = (const float*)d_in[i];
    else if (in_sizes[i] == 8 * 128 * 128 * 36) high1 = (const float*)d_in[i];
  }
  float* out = (float*)d_out;

  const int T = 256;
  const int N1 = 8 * 512 * 256 * 3;   // 3,145,728
  const int N2 = 8 * 512 * 512 * 3;   // 6,291,456

  k1_lvl1_vert<<<(N1 + T - 1) / T, T>>>(low, high1);
  k2_lvl1_horz<<<(N2 + T - 1) / T, T>>>();
  k3_lvl0_vert<<<(N2 + T - 1) / T, T>>>(high0);
  k4_lvl0_horz<<<(N2 + T - 1) / T, T>>>(out);
}

// round 2
// speedup vs baseline: 2.1649x; 2.1649x over previous
#include <cuda_runtime.h>

// ---------------------------------------------------------------------------
// Inverse DTCWT, 2 levels. Shapes (fixed):
//   low   : (8, 256, 256, 3)
//   high0 : (8, 256, 256, 36)
//   high1 : (8, 128, 128, 36)
//   out   : (8, 512, 512, 3)
// Each thread computes 4 consecutive outputs along the filter axis, sharing
// one source window (14 taps for qshift, 10/8 for biort).
// ---------------------------------------------------------------------------

#define SCQ 0.70710678118654752f

// qshift per-phase polyphase filters. For outputs n = 4k+s, all taps lie in
// the window x[2k-6 .. 2k+7] (window coord v = p - (2k-6)).
// F0 taps at v = 12+(s&1)-2j ; F1 taps at v = 13-(s&1)-2j, j=0..6.
__constant__ float cF0[4][7] = {
  { 0.00325314f,  0.03466035f, -0.11720389f,  0.75614564f,  0.01186609f,  0.02382538f, -0.00543948f},
  {-0.00455690f,  0.01702522f, -0.10671180f,  0.56881042f,  0.27529538f, -0.03887280f, -0.00388321f},
  {-0.00388321f, -0.03887280f,  0.27529538f,  0.56881042f, -0.10671180f,  0.01702522f, -0.00455690f},
  {-0.00543948f,  0.02382538f,  0.01186609f,  0.75614564f, -0.11720389f,  0.03466035f,  0.00325314f}
};
__constant__ float cF1[4][7] = {
  {-0.00455690f,  0.01702522f, -0.10671180f,  0.56881042f,  0.27529538f, -0.03887280f, -0.00388321f},
  {-0.00325314f, -0.03466035f,  0.11720389f, -0.75614564f, -0.01186609f, -0.02382538f,  0.00543948f},
  { 0.00543948f, -0.02382538f, -0.01186609f, -0.75614564f,  0.11720389f, -0.03466035f, -0.00325314f},
  {-0.00388321f, -0.03887280f,  0.27529538f,  0.56881042f, -0.10671180f,  0.01702522f, -0.00455690f}
};
__constant__ float cG0[7] = {-0.0107142857142857f, -0.0535714285714286f, 0.2607142857142857f,
                              0.6071428571428571f,  0.2607142857142857f, -0.0535714285714286f,
                             -0.0107142857142857f};
__constant__ float cG1[5] = {-0.05f, -0.25f, 0.6f, -0.25f, -0.05f};

// scratch (device globals; no allocations allowed)
__device__ float g_Y1 [8 * 512 * 256 * 3];
__device__ float g_Y2 [8 * 512 * 256 * 3];
__device__ float g_Z  [8 * 512 * 512 * 3];
__device__ float g_Y1b[8 * 512 * 512 * 3];
__device__ float g_Y2b[8 * 512 * 512 * 3];

__device__ __forceinline__ int refl(int p, int L) {
  return p < 0 ? (-1 - p) : (p >= L ? (2 * L - 1 - p) : p);
}

// combine the two subband samples into the c2q value (SC applied by caller)
__device__ __forceinline__ float comb(float x, float y, int rp, int wp) {
  return rp == 0 ? (x + y) : (wp == 0 ? (x - y) : (y - x));
}

// ---------------- K1: level-1 vertical (qshift colifilt over H) -------------
// outputs n = 4k+s (512 rows) at fixed (b, w, c); sources have 256 rows.
__global__ void k1_lvl1_vert(const float* __restrict__ low, const float* __restrict__ hi1) {
  int u = blockIdx.x * 256 + threadIdx.x;   // 0..767 = 3*w+c
  int k = blockIdx.y;                        // 0..127
  int b = blockIdx.z;
  int w = u / 3, c = u - 3 * w;
  int jj = w >> 1, wp = w & 1;
  const bool interior = (k >= 3 && k <= 124);
  const int base = 2 * k - 6;

  const float* lowb = low + ((b * 256) * 256 + w) * 3 + c;      // + pr*768
  const float* hb   = hi1 + ((b * 128) * 128 + jj) * 36 + c;    // + i*4608

  float xl[14], xlh[14], xhl[14], xhh[14];
#pragma unroll
  for (int v = 0; v < 14; v++) {
    int p = base + v;
    int pr = interior ? p : refl(p, 256);
    xl[v] = lowb[pr * 768];
    int i = pr >> 1, rp = pr & 1;
    const float* q = hb + i * 4608 + ((rp ^ wp) ? 18 : 0);
    xlh[v] = comb(q[0], q[15], rp, wp);
    xhl[v] = comb(q[6], q[9],  rp, wp);
    xhh[v] = comb(q[3], q[12], rp, wp);
  }

  float A[4], LH[4], HL[4], HH[4];
#pragma unroll
  for (int s = 0; s < 4; s++) { A[s]=0.f; LH[s]=0.f; HL[s]=0.f; HH[s]=0.f; }
#pragma unroll
  for (int s = 0; s < 4; s++) {
    int v0 = 12 + (s & 1), v1 = 13 - (s & 1);
#pragma unroll
    for (int j = 0; j < 7; j++) {
      float f0 = cF0[s][j], f1 = cF1[s][j];
      A[s]  += f0 * xl [v0 - 2*j];
      HL[s] += f0 * xhl[v0 - 2*j];
      LH[s] += f1 * xlh[v1 - 2*j];
      HH[s] += f1 * xhh[v1 - 2*j];
    }
  }
  int ob = ((b * 512 + 4 * k) * 256 + w) * 3 + c;   // row stride 768
#pragma unroll
  for (int s = 0; s < 4; s++) {
    g_Y1[ob + s * 768] = A[s] + SCQ * LH[s];
    g_Y2[ob + s * 768] = SCQ * (HL[s] + HH[s]);
  }
}

// ---------------- K2: level-1 horizontal (qshift colifilt over W) -----------
__global__ void k2_lvl1_horz() {
  int t = threadIdx.x;            // 384: (k,c)
  int k = t / 3, c = t - 3 * k;   // k 0..127
  int h = blockIdx.x, b = blockIdx.y;
  const bool interior = (k >= 3 && k <= 124);
  const int base = 2 * k - 6;
  int rb = ((b * 512 + h) * 256) * 3 + c;

  float x1[14], x2[14];
#pragma unroll
  for (int v = 0; v < 14; v++) {
    int p = base + v;
    int pr = interior ? p : refl(p, 256);
    x1[v] = g_Y1[rb + pr * 3];
    x2[v] = g_Y2[rb + pr * 3];
  }
  int ob = ((b * 512 + h) * 512 + 4 * k) * 3 + c;
#pragma unroll
  for (int s = 0; s < 4; s++) {
    int v0 = 12 + (s & 1), v1 = 13 - (s & 1);
    float acc = 0.f;
#pragma unroll
    for (int j = 0; j < 7; j++)
      acc += cF0[s][j] * x1[v0 - 2*j] + cF1[s][j] * x2[v1 - 2*j];
    g_Z[ob + s * 3] = acc;
  }
}

// ---------------- K3: level-0 vertical (biort colfilter over H) -------------
// 4 consecutive rows r = 4q+s; G0O window [r0-3, r0+6], G1O window [r0-2, r0+5].
__global__ void k3_lvl0_vert(const float* __restrict__ hi0) {
  int u = blockIdx.x * 256 + threadIdx.x;   // 0..1535
  int q = blockIdx.y;                        // 0..127
  int b = blockIdx.z;
  int w = u / 3, c = u - 3 * w;
  int jj = w >> 1, wp = w & 1;
  int r0 = 4 * q;
  const bool interior = (q >= 1 && q <= 125);

  const float* zb = g_Z + ((b * 512) * 512 + w) * 3 + c;        // + pr*1536
  const float* hb = hi0 + ((b * 256) * 256 + jj) * 36 + c;      // + i*9216

  float xz[10], xhl[10], xlh[8], xhh[8];
#pragma unroll
  for (int v = 0; v < 10; v++) {
    int p = r0 - 3 + v;
    int pr = interior ? p : refl(p, 512);
    xz[v] = zb[pr * 1536];
    int i = pr >> 1, rp = pr & 1;
    const float* qq = hb + i * 9216 + ((rp ^ wp) ? 18 : 0);
    xhl[v] = comb(qq[6], qq[9], rp, wp);
  }
#pragma unroll
  for (int v = 0; v < 8; v++) {
    int p = r0 - 2 + v;
    int pr = interior ? p : refl(p, 512);
    int i = pr >> 1, rp = pr & 1;
    const float* qq = hb + i * 9216 + ((rp ^ wp) ? 18 : 0);
    xlh[v] = comb(qq[0], qq[15], rp, wp);
    xhh[v] = comb(qq[3], qq[12], rp, wp);
  }
  int ob = ((b * 512 + r0) * 512 + w) * 3 + c;   // row stride 1536
#pragma unroll
  for (int s = 0; s < 4; s++) {
    float a = 0.f, hl = 0.f, lh = 0.f, hh = 0.f;
#pragma unroll
    for (int j = 0; j < 7; j++) {
      float f = cG0[j];
      a  += f * xz [s + 6 - j];
      hl += f * xhl[s + 6 - j];
    }
#pragma unroll
    for (int j = 0; j < 5; j++) {
      float f = cG1[j];
      lh += f * xlh[s + 4 - j];
      hh += f * xhh[s + 4 - j];
    }
    g_Y1b[ob + s * 1536] = a + SCQ * lh;
    g_Y2b[ob + s * 1536] = SCQ * (hl + hh);
  }
}

// ---------------- K4: level-0 horizontal (biort colfilter over W) -----------
__global__ void k4_lvl0_horz(float* __restrict__ out) {
  int t = threadIdx.x;            // 384
  int q = t / 3, c = t - 3 * q;   // q 0..127
  int h = blockIdx.x, b = blockIdx.y;
  int w0 = 4 * q;
  const bool interior = (q >= 1 && q <= 125);
  int rb = ((b * 512 + h) * 512) * 3 + c;

  float x1[10], x2[8];
#pragma unroll
  for (int v = 0; v < 10; v++) {
    int p = w0 - 3 + v;
    int pr = interior ? p : refl(p, 512);
    x1[v] = g_Y1b[rb + pr * 3];
  }
#pragma unroll
  for (int v = 0; v < 8; v++) {
    int p = w0 - 2 + v;
    int pr = interior ? p : refl(p, 512);
    x2[v] = g_Y2b[rb + pr * 3];
  }
  int ob = rb + w0 * 3;
#pragma unroll
  for (int s = 0; s < 4; s++) {
    float acc = 0.f;
#pragma unroll
    for (int j = 0; j < 7; j++) acc += cG0[j] * x1[s + 6 - j];
#pragma unroll
    for (int j = 0; j < 5; j++) acc += cG1[j] * x2[s + 4 - j];
    out[ob + s * 3] = acc;
  }
}

extern "C" void kernel_launch(void* const* d_in, const int* in_sizes, int n_in,
                              void* d_out, int out_size) {
  const float *low = nullptr, *high0 = nullptr, *high1 = nullptr;
  for (int i = 0; i < n_in; i++) {
    if (in_sizes[i] == 8 * 256 * 256 * 3)       low   = (const float*)d_in[i];
    else if (in_sizes[i] == 8 * 256 * 256 * 36) high0 = (const float*)d_in[i];
    else if (in_sizes[i] == 8 * 128 * 128 * 36) high1 = (const float*)d_in[i];
  }
  float* out = (float*)d_out;

  k1_lvl1_vert<<<dim3(3, 128, 8), 256>>>(low, high1);
  k2_lvl1_horz<<<dim3(512, 8), 384>>>();
  k3_lvl0_vert<<<dim3(6, 128, 8), 256>>>(high0);
  k4_lvl0_horz<<<dim3(512, 8), 384>>>(out);
}